// round 14
// baseline (speedup 1.0000x reference)
#include <cuda_runtime.h>
#include <cuda_fp16.h>
#include <math.h>
#include <stdint.h>

#define B_   4
#define S_   8192
#define H_   768
#define NH_  12
#define HD_  64
#define NB_  64
#define TOT_ (B_*S_*H_)

// attention smem strides
#define QSTU 36    // u32 stride for fp16 Q/K/V rows (32 u32 data + 4 pad)
#define PSTU 68    // u32 stride for fp16 P rows (64 u32 data + 4 pad)
#define SST  132   // fp32 score stride (even: float2 stores stay 8B-aligned)

// fp16 gemm config: BK=32 halves
#define GST   20                   // u32 stride per 32-half row
#define GSTG  (128 * GST)
#define GNSTG 3
#define GKT   24                   // 768 / 32
#define GSMEM (2 * GNSTG * GSTG * 4)   // 61440 B

// ---------------- scratch (device globals; no allocs allowed) ----------------
__device__ __half g_HH[TOT_];
__device__ __half g_RELH[512 * H_];
__device__ __half g_WTh[4 * H_ * H_];
__device__ __half g_Qh[TOT_];
__device__ __half g_Kh[TOT_];
__device__ __half g_Vh[TOT_];
__device__ __half g_CTH[TOT_];
__device__ float  g_XR[TOT_];
__device__ float  g_PK[512 * H_];
__device__ float  g_PQ[512 * H_];
__device__ __half g_PKH[NH_ * 512 * HD_];
__device__ __half g_PQH[NH_ * 512 * HD_];

// ---------------- helpers -----------------------------------------------------
__device__ __forceinline__ void mma_f16(float* c, const uint32_t* a, const uint32_t* b) {
    asm volatile(
        "mma.sync.aligned.m16n8k16.row.col.f32.f16.f16.f32 "
        "{%0,%1,%2,%3},{%4,%5,%6,%7},{%8,%9},{%0,%1,%2,%3};\n"
        : "+f"(c[0]), "+f"(c[1]), "+f"(c[2]), "+f"(c[3])
        : "r"(a[0]), "r"(a[1]), "r"(a[2]), "r"(a[3]), "r"(b[0]), "r"(b[1]));
}

__device__ __forceinline__ void ldsm_x4(
    uint32_t& r0, uint32_t& r1, uint32_t& r2, uint32_t& r3, uint32_t addr)
{
    asm volatile(
        "ldmatrix.sync.aligned.m8n8.x4.shared.b16 {%0,%1,%2,%3}, [%4];"
        : "=r"(r0), "=r"(r1), "=r"(r2), "=r"(r3) : "r"(addr));
}

__device__ __forceinline__ void ldsm_x4_t(
    uint32_t& r0, uint32_t& r1, uint32_t& r2, uint32_t& r3, uint32_t addr)
{
    asm volatile(
        "ldmatrix.sync.aligned.m8n8.x4.trans.shared.b16 {%0,%1,%2,%3}, [%4];"
        : "=r"(r0), "=r"(r1), "=r"(r2), "=r"(r3) : "r"(addr));
}

__device__ __forceinline__ void cp16u(uint32_t* dst_smem, const void* src) {
    uint32_t d = (uint32_t)__cvta_generic_to_shared(dst_smem);
    asm volatile("cp.async.cg.shared.global [%0], [%1], 16;\n" :: "r"(d), "l"(src));
}
__device__ __forceinline__ void cp_commit() {
    asm volatile("cp.async.commit_group;\n");
}

__device__ __forceinline__ uint32_t ex2_f16x2(uint32_t x) {
    uint32_t r;
    asm volatile("ex2.approx.f16x2 %0, %1;" : "=r"(r) : "r"(x));
    return r;
}

// ---------------- conversion kernels -----------------------------------------
__global__ void __launch_bounds__(256) f2h_kernel(
    const float* __restrict__ x, __half* __restrict__ y)
{
    size_t i = ((size_t)blockIdx.x * 256 + threadIdx.x) * 4;
    float4 v = *(const float4*)(x + i);
    *(__half2*)(y + i)     = __floats2half2_rn(v.x, v.y);
    *(__half2*)(y + i + 2) = __floats2half2_rn(v.z, v.w);
}

// 4 weights transposed in one launch: WT[z][n][k] = fp16(W[z][k][n])
__global__ void __launch_bounds__(256) transpose768h4(
    const float* __restrict__ W0, const float* __restrict__ W1,
    const float* __restrict__ W2, const float* __restrict__ W3,
    __half* __restrict__ WT)
{
    __shared__ float t[32][33];
    const float* W = (blockIdx.z == 0) ? W0 : (blockIdx.z == 1) ? W1
                   : (blockIdx.z == 2) ? W2 : W3;
    __half* WTz = WT + (size_t)blockIdx.z * H_ * H_;
    int x = blockIdx.x * 32 + threadIdx.x;
    int y = blockIdx.y * 32 + threadIdx.y;
    #pragma unroll
    for (int i = 0; i < 32; i += 8)
        t[threadIdx.y + i][threadIdx.x] = W[(size_t)(y + i) * H_ + x];
    __syncthreads();
    x = blockIdx.y * 32 + threadIdx.x;
    y = blockIdx.x * 32 + threadIdx.y;
    #pragma unroll
    for (int i = 0; i < 32; i += 8)
        WTz[(size_t)(y + i) * H_ + x] = __float2half_rn(t[threadIdx.x][threadIdx.y + i]);
}

// ---------------- shared GEMM body: 128x128 tile, 4 warps of 64x64 -----------
// 3-stage cp.async, single sync/iter, ldmatrix fragments.
__device__ __forceinline__ void gemm_body(
    const __half* __restrict__ A, const __half* __restrict__ Bw,
    const float* __restrict__ bias, const float* __restrict__ Rres,
    float* __restrict__ Cf, __half* __restrict__ Ch,
    int bm, int bn, uint32_t* gsm)
{
    uint32_t* As = gsm;
    uint32_t* Bs = gsm + GNSTG * GSTG;

    const int tid  = threadIdx.x;        // 0..127
    const int lane = tid & 31;
    const int warp = tid >> 5;           // 0..3
    const int wm   = (warp & 1) * 64;    // 2m x 2n of 64x64 warp tiles
    const int wn   = (warp >> 1) * 64;
    const int gid  = lane >> 2;
    const int tig  = lane & 3;
    const int lr16 = lane & 15;
    const int lc4  = (lane >> 4) << 2;

    const uint32_t as0 = (uint32_t)__cvta_generic_to_shared(As);
    const uint32_t bs0 = (uint32_t)__cvta_generic_to_shared(Bs);

    float acc[4][8][4];
    #pragma unroll
    for (int mt = 0; mt < 4; mt++)
        #pragma unroll
        for (int nt = 0; nt < 8; nt++)
            #pragma unroll
            for (int i = 0; i < 4; i++) acc[mt][nt][i] = 0.f;

    auto fill = [&](int s, int kt) {
        const int kb = kt * 32;
        const __half* Ab = A  + (size_t)(bm + tid) * H_ + kb;
        const __half* Bb = Bw + (size_t)(bn + tid) * H_ + kb;
        uint32_t* as = As + s * GSTG + tid * GST;
        uint32_t* bs = Bs + s * GSTG + tid * GST;
        #pragma unroll
        for (int c2 = 0; c2 < 4; c2++) {
            cp16u(&as[c2 * 4], Ab + c2 * 8);
            cp16u(&bs[c2 * 4], Bb + c2 * 8);
        }
        cp_commit();
    };

    fill(0, 0);
    fill(1, 1);

    for (int kt = 0; kt < GKT; kt++) {
        if (kt < GKT - 1) asm volatile("cp.async.wait_group 1;\n");
        else              asm volatile("cp.async.wait_group 0;\n");
        __syncthreads();

        const uint32_t asb = as0 + (uint32_t)((kt % GNSTG) * GSTG) * 4;
        const uint32_t bsb = bs0 + (uint32_t)((kt % GNSTG) * GSTG) * 4;

        #pragma unroll
        for (int ks = 0; ks < 2; ks++) {
            const int wb = ks * 8;
            uint32_t a[4][4], b[8][2];
            #pragma unroll
            for (int mt = 0; mt < 4; mt++)
                ldsm_x4(a[mt][0], a[mt][1], a[mt][2], a[mt][3],
                        asb + (uint32_t)(((wm + mt * 16 + lr16) * GST + wb + lc4) * 4));
            #pragma unroll
            for (int ntp = 0; ntp < 4; ntp++) {
                uint32_t r0, r1, r2, r3;
                ldsm_x4(r0, r1, r2, r3,
                        bsb + (uint32_t)(((wn + ntp * 16 + lr16) * GST + wb + lc4) * 4));
                b[2 * ntp][0]     = r0;
                b[2 * ntp + 1][0] = r1;
                b[2 * ntp][1]     = r2;
                b[2 * ntp + 1][1] = r3;
            }
            #pragma unroll
            for (int mt = 0; mt < 4; mt++)
                #pragma unroll
                for (int nt = 0; nt < 8; nt++)
                    mma_f16(acc[mt][nt], a[mt], b[nt]);
        }
        // fill stage freed by compute(kt-1); safe after this iteration's sync
        if (kt + 2 < GKT) fill((kt + 2) % GNSTG, kt + 2);
    }

    #pragma unroll
    for (int mt = 0; mt < 4; mt++) {
        #pragma unroll
        for (int hi = 0; hi < 2; hi++) {
            size_t row = (size_t)bm + wm + mt * 16 + gid + hi * 8;
            #pragma unroll
            for (int nt = 0; nt < 8; nt++) {
                int col = bn + wn + nt * 8 + tig * 2;
                float v0 = acc[mt][nt][hi * 2 + 0] + bias[col];
                float v1 = acc[mt][nt][hi * 2 + 1] + bias[col + 1];
                if (Rres != nullptr) {
                    float2 rr = *(const float2*)(Rres + row * (size_t)H_ + col);
                    v0 += rr.x; v1 += rr.y;
                }
                if (Cf != nullptr)
                    *(float2*)(Cf + row * (size_t)H_ + col) = make_float2(v0, v1);
                else
                    *(__half2*)(Ch + row * (size_t)H_ + col) = __floats2half2_rn(v0, v1);
            }
        }
    }
}

// QKV in one launch: blockIdx.x/6 selects {Q,K,V}
__global__ void __launch_bounds__(128, 2) qkv_gemm(
    const __half* __restrict__ A, const __half* __restrict__ WT,
    const float* __restrict__ bq, const float* __restrict__ bk,
    const float* __restrict__ bv,
    __half* __restrict__ Oq, __half* __restrict__ Ok, __half* __restrict__ Ov)
{
    extern __shared__ uint32_t gsm[];
    const int which = blockIdx.x / 6;
    const int bn = (blockIdx.x % 6) * 128;
    const int bm = blockIdx.y * 128;
    const __half* Bw = WT + (size_t)which * H_ * H_;
    const float* bias = (which == 0) ? bq : (which == 1) ? bk : bv;
    __half* Ch = (which == 0) ? Oq : (which == 1) ? Ok : Ov;
    gemm_body(A, Bw, bias, nullptr, nullptr, Ch, bm, bn, gsm);
}

// both pos projections in one launch: blockIdx.x/6 selects {PK(Wk), PQ(Wq)}
__global__ void __launch_bounds__(128, 2) pos_gemm(
    const __half* __restrict__ A, const __half* __restrict__ WT,
    const float* __restrict__ bq, const float* __restrict__ bk,
    float* __restrict__ Opk, float* __restrict__ Opq)
{
    extern __shared__ uint32_t gsm[];
    const int which = blockIdx.x / 6;
    const int bn = (blockIdx.x % 6) * 128;
    const int bm = blockIdx.y * 128;
    const __half* Bw = WT + (size_t)(which == 0 ? 1 : 0) * H_ * H_; // Wk else Wq
    const float* bias = (which == 0) ? bk : bq;
    float* Cf = (which == 0) ? Opk : Opq;
    gemm_body(A, Bw, bias, nullptr, Cf, nullptr, bm, bn, gsm);
}

// out-proj with residual, fp32 out
__global__ void __launch_bounds__(128, 2) out_gemm(
    const __half* __restrict__ A, const __half* __restrict__ WT,
    const float* __restrict__ bias, const float* __restrict__ Rres,
    float* __restrict__ Cf)
{
    extern __shared__ uint32_t gsm[];
    const int bn = blockIdx.x * 128;
    const int bm = blockIdx.y * 128;
    gemm_body(A, WT, bias, Rres, Cf, nullptr, bm, bn, gsm);
}

// ---------------- bucketization + fp16 pos tables ----------------------------
__device__ __forceinline__ int bucket_idx_dev(int d)
{
    int ad = d < 0 ? -d : d;
    int v;
    if (ad <= 128) {
        v = d;
    } else {
        float t = logf((float)ad / 128.0f);
        t = t / 0.6892332713f;                   // fp32(ln(255/128))
        t = t * 127.0f;
        float lp = ceilf(t) + 128.0f;
        v = (int)(d < 0 ? -lp : lp);
    }
    v += 256;
    return v < 0 ? 0 : (v > 511 ? 511 : v);
}

__global__ void build_pos_h(const float* __restrict__ PK, const float* __restrict__ PQ,
                            __half* __restrict__ PKH, __half* __restrict__ PQH)
{
    int dd = blockIdx.x;                         // 0..510
    int t  = threadIdx.x;                        // 0..767
    int p  = bucket_idx_dev(dd - 383);
    int h  = t >> 6;
    int d  = t & 63;
    size_t dst = ((size_t)h * 512 + dd + 1) * HD_ + d;
    PKH[dst] = __float2half_rn(PK[(size_t)p * H_ + t]);
    PQH[dst] = __float2half_rn(PQ[(size_t)p * H_ + t]);
    if (dd == 0) {
        PKH[((size_t)h * 512) * HD_ + d] = __float2half_rn(0.f);
        PQH[((size_t)h * 512) * HD_ + d] = __float2half_rn(0.f);
    }
}

// ---------------- attention: fp16 MMA, exact-window C2P/P2C ------------------
__global__ void __launch_bounds__(256, 1) attn_mma(
    const __half* __restrict__ Qh, const __half* __restrict__ Kh,
    const __half* __restrict__ Vh,
    const __half* __restrict__ PKH, const __half* __restrict__ PQH,
    __half* __restrict__ CTH)
{
    extern __shared__ char smc[];
    uint32_t* Qsu = (uint32_t*)smc;                       // 128*QSTU
    uint32_t* Ksu = Qsu + 128 * QSTU;
    uint32_t* Vsu = Ksu + 128 * QSTU;
    uint32_t* Phu = Vsu + 128 * QSTU;                     // 128*PSTU
    float* Ss   = (float*)(Phu + 128 * PSTU);             // 128*SST
    float* mrow = Ss + 128 * SST;                         // 128
    float* lrow = mrow + 128;
    float* crow = lrow + 128;

    const int h = blockIdx.x, n = blockIdx.y, b = blockIdx.z;
    const int tid  = threadIdx.x;
    const int lane = tid & 31;
    const int warp = tid >> 5;
    const int gid  = lane >> 2;
    const int tig  = lane & 3;
    const int lr16 = lane & 15;
    const int lc4  = (lane >> 4) << 2;
    const size_t qrow0 = (size_t)b * S_ + (size_t)n * 128;
    const size_t hoff  = (size_t)h * HD_;

    const uint32_t qbase = (uint32_t)__cvta_generic_to_shared(Qsu);
    const uint32_t kbase = (uint32_t)__cvta_generic_to_shared(Ksu);
    const uint32_t vbase = (uint32_t)__cvta_generic_to_shared(Vsu);
    const uint32_t pbase = (uint32_t)__cvta_generic_to_shared(Phu);

    for (int i = tid; i < 128 * 8; i += 256) {
        int r = i >> 3, c = i & 7;
        uint4 v = *(const uint4*)(Qh + (qrow0 + r) * H_ + hoff + c * 8);
        uint32_t* d = &Qsu[r * QSTU + c * 4];
        d[0] = v.x; d[1] = v.y; d[2] = v.z; d[3] = v.w;
    }
    if (tid < 128) { mrow[tid] = -1e30f; lrow[tid] = 0.f; }
    __syncthreads();

    float ctx[8][4];
    #pragma unroll
    for (int nt = 0; nt < 8; nt++)
        #pragma unroll
        for (int i = 0; i < 4; i++) ctx[nt][i] = 0.f;

    const uint32_t* pk32 = (const uint32_t*)PKH + (size_t)h * 512 * 32;
    const uint32_t* pq32 = (const uint32_t*)PQH + (size_t)h * 512 * 32;
    const float scale = 0.07216878364870323f;    // 1/sqrt(192)
    const float L2E   = 1.4426950408889634f;

    const int lg  = lane >> 3;
    const int lr  = lane & 7;
    const int vkb = (lg & 1) * 8 + lr;
    const int vnb = (lg >> 1) * 8;

    for (int c = 0; c < 3; c++) {
        const int  c0  = c * 128;
        const long sk0 = (long)n * 128 - 128 + c0;

        for (int i = tid; i < 128 * 8; i += 256) {
            int r = i >> 3, cc = i & 7;
            long s = sk0 + r;
            uint4 kv = make_uint4(0u, 0u, 0u, 0u);
            uint4 vv = make_uint4(0u, 0u, 0u, 0u);
            if (s >= 0 && s < S_) {
                size_t g = ((size_t)b * S_ + s) * H_ + hoff + cc * 8;
                kv = *(const uint4*)(Kh + g);
                vv = *(const uint4*)(Vh + g);
            }
            uint32_t* dk = &Ksu[r * QSTU + cc * 4];
            dk[0] = kv.x; dk[1] = kv.y; dk[2] = kv.z; dk[3] = kv.w;
            uint32_t* dv = &Vsu[r * QSTU + cc * 4];
            dv[0] = vv.x; dv[1] = vv.y; dv[2] = vv.z; dv[3] = vv.w;
        }
        __syncthreads();

        // ---- c2c ----
        {
            const int wm = (warp & 3) * 32, wn = (warp >> 2) * 64;
            float acc[2][8][4];
            #pragma unroll
            for (int mt = 0; mt < 2; mt++)
                #pragma unroll
                for (int nt = 0; nt < 8; nt++)
                    #pragma unroll
                    for (int i = 0; i < 4; i++) acc[mt][nt][i] = 0.f;

            #pragma unroll
            for (int ks = 0; ks < 4; ks++) {
                const int wb = ks * 8;
                uint32_t a[2][4], bf[8][2];
                #pragma unroll
                for (int mt = 0; mt < 2; mt++)
                    ldsm_x4(a[mt][0], a[mt][1], a[mt][2], a[mt][3],
                            qbase + (uint32_t)(((wm + mt * 16 + lr16) * QSTU + wb + lc4) * 4));
                #pragma unroll
                for (int ntp = 0; ntp < 4; ntp++) {
                    uint32_t r0, r1, r2, r3;
                    ldsm_x4(r0, r1, r2, r3,
                            kbase + (uint32_t)(((wn + ntp * 16 + lr16) * QSTU + wb + lc4) * 4));
                    bf[2 * ntp][0]     = r0;
                    bf[2 * ntp + 1][0] = r1;
                    bf[2 * ntp][1]     = r2;
                    bf[2 * ntp + 1][1] = r3;
                }
                #pragma unroll
                for (int mt = 0; mt < 2; mt++)
                    #pragma unroll
                    for (int nt = 0; nt < 8; nt++)
                        mma_f16(acc[mt][nt], a[mt], bf[nt]);
            }
            #pragma unroll
            for (int mt = 0; mt < 2; mt++) {
                int r1 = wm + mt * 16 + gid;
                #pragma unroll
                for (int nt = 0; nt < 8; nt++) {
                    int cc = wn + nt * 8 + 2 * tig;
                    *(float2*)&Ss[r1 * SST + cc] =
                        make_float2(acc[mt][nt][0], acc[mt][nt][1]);
                    *(float2*)&Ss[(r1 + 8) * SST + cc] =
                        make_float2(acc[mt][nt][2], acc[mt][nt][3]);
                }
            }
        }
        __syncthreads();

        // ---- C2P: exact window [wm, wm+160), warp pair splits 80+80 ---------
        {
            const int wm = (warp & 3) * 32;
            const int wg = warp >> 2;
            const int colbase = 256 - c0;
            const int ws = wm + wg * 80;
            float acc[2][10][4];
            #pragma unroll
            for (int mt = 0; mt < 2; mt++)
                #pragma unroll
                for (int nt = 0; nt < 10; nt++)
                    #pragma unroll
                    for (int i = 0; i < 4; i++) acc[mt][nt][i] = 0.f;

            #pragma unroll
            for (int ks = 0; ks < 4; ks++) {
                const int wb = ks * 8;
                uint32_t a[2][4];
                #pragma unroll
                for (int mt = 0; mt < 2; mt++)
                    ldsm_x4(a[mt][0], a[mt][1], a[mt][2], a[mt][3],
                            qbase + (uint32_t)(((wm + mt * 16 + lr16) * QSTU + wb + lc4) * 4));
                #pragma unroll
                for (int nt = 0; nt < 10; nt++) {
                    int cc = colbase + ws + nt * 8 + gid;
                    uint32_t bf[2];
                    bf[0] = __ldg(&pk32[(size_t)cc * 32 + wb + tig]);
                    bf[1] = __ldg(&pk32[(size_t)cc * 32 + wb + 4 + tig]);
                    mma_f16(acc[0][nt], a[0], bf);
                    mma_f16(acc[1][nt], a[1], bf);
                }
            }
            #pragma unroll
            for (int mt = 0; mt < 2; mt++) {
                int r1 = wm + mt * 16 + gid;
                #pragma unroll
                for (int nt = 0; nt < 10; nt++) {
                    int ci = ws + nt * 8 + 2 * tig;
                    int jj;
                    jj = r1 - ci + 128;
                    if (jj >= 0 && jj < 128) Ss[r1 * SST + jj] += acc[mt][nt][0];
                    jj = r1 - ci + 127;
                    if (jj >= 0 && jj < 128) Ss[r1 * SST + jj] += acc[mt][nt][1];
                    int r2 = r1 + 8;
                    jj = r2 - ci + 128;
                    if (jj >= 0 && jj < 128) Ss[r2 * SST + jj] += acc[mt][nt][2];
                    jj = r2 - ci + 127;
                    if (jj >= 0 && jj < 128) Ss[r2 * SST + jj] += acc[mt][nt][3];
                }
            }
        }
        __syncthreads();

        // ---- P2C: exact window [96-wm, 256-wm), warp pair splits 80+80 ------
        {
            const int wm = (warp & 3) * 32;
            const int wg = warp >> 2;
            const int colbase = 256 - c0;
            const int ws = (96 - wm) + wg * 80;
            float acc[2][10][4];
            #pragma unroll
            for (int mt = 0; mt < 2; mt++)
                #pragma unroll
                for (int nt = 0; nt < 10; nt++)
                    #pragma unroll
                    for (int i = 0; i < 4; i++) acc[mt][nt][i] = 0.f;

            #pragma unroll
            for (int ks = 0; ks < 4; ks++) {
                const int wb = ks * 8;
                uint32_t a[2][4];
                #pragma unroll
                for (int mt = 0; mt < 2; mt++)
                    ldsm_x4(a[mt][0], a[mt][1], a[mt][2], a[mt][3],
                            kbase + (uint32_t)(((wm + mt * 16 + lr16) * QSTU + wb + lc4) * 4));
                #pragma unroll
                for (int nt = 0; nt < 10; nt++) {
                    int cc = colbase + ws + nt * 8 + gid;
                    uint32_t bf[2];
                    bf[0] = __ldg(&pq32[(size_t)cc * 32 + wb + tig]);
                    bf[1] = __ldg(&pq32[(size_t)cc * 32 + wb + 4 + tig]);
                    mma_f16(acc[0][nt], a[0], bf);
                    mma_f16(acc[1][nt], a[1], bf);
                }
            }
            #pragma unroll
            for (int mt = 0; mt < 2; mt++) {
                int r1 = wm + mt * 16 + gid;
                #pragma unroll
                for (int nt = 0; nt < 10; nt++) {
                    int ci = ws + nt * 8 + 2 * tig;
                    int q;
                    q = r1 + ci - 128;
                    if (q >= 0 && q < 128) Ss[q * SST + r1] += acc[mt][nt][0];
                    q = r1 + ci - 127;
                    if (q >= 0 && q < 128) Ss[q * SST + r1] += acc[mt][nt][1];
                    int r2 = r1 + 8;
                    q = r2 + ci - 128;
                    if (q >= 0 && q < 128) Ss[q * SST + r2] += acc[mt][nt][2];
                    q = r2 + ci - 127;
                    if (q >= 0 && q < 128) Ss[q * SST + r2] += acc[mt][nt][3];
                }
            }
        }
        __syncthreads();

        // ---- online softmax: lane-pair per row, shuffle reductions, ex2 -----
        {
            const int r  = tid >> 1;
            const int hh = tid & 1;
            float* srow = Ss + r * SST + hh * 64;
            float mx = -1e30f;
            #pragma unroll 8
            for (int j = 0; j < 64; j++) mx = fmaxf(mx, srow[j]);
            mx = fmaxf(mx, __shfl_xor_sync(0xffffffffu, mx, 1));

            float mold = mrow[r];
            float mnew = fmaxf(mold, mx * scale);
            float corr = exp2f((mold - mnew) * L2E);

            const float sl = scale * L2E;
            const float ml = mnew * L2E;
            float ssum = 0.f;
            uint32_t* prow = Phu + r * PSTU + hh * 32;
            #pragma unroll 8
            for (int j = 0; j < 64; j += 2) {
                float t0 = fmaf(srow[j],     sl, -ml);
                float t1 = fmaf(srow[j + 1], sl, -ml);
                __half2 th = __floats2half2_rn(t0, t1);
                uint32_t ph = ex2_f16x2(*(uint32_t*)&th);
                prow[j >> 1] = ph;
                float2 pf = __half22float2(*(__half2*)&ph);
                ssum += pf.x + pf.y;
            }
            ssum += __shfl_xor_sync(0xffffffffu, ssum, 1);
            if (hh == 0) {
                crow[r] = corr;
                mrow[r] = mnew;
                lrow[r] = lrow[r] * corr + ssum;
            }
        }
        __syncthreads();

        // ---- PV ----
        {
            const int wm1 = warp * 16;
            float c1 = crow[wm1 + gid], c2 = crow[wm1 + gid + 8];
            #pragma unroll
            for (int nt = 0; nt < 8; nt++) {
                ctx[nt][0] *= c1; ctx[nt][1] *= c1;
                ctx[nt][2] *= c2; ctx[nt][3] *= c2;
            }
            #pragma unroll
            for (int ks = 0; ks < 8; ks++) {
                uint32_t a[4];
                ldsm_x4(a[0], a[1], a[2], a[3],
                        pbase + (uint32_t)(((wm1 + lr16) * PSTU + ks * 8 + lc4) * 4));
                uint32_t vaddr = vbase +
                    (uint32_t)((16 * ks + vkb) * (QSTU * 4)) + (uint32_t)(vnb * 2);
                #pragma unroll
                for (int ntp = 0; ntp < 4; ntp++) {
                    uint32_t b0, b1, b2, b3;
                    ldsm_x4_t(b0, b1, b2, b3, vaddr + ntp * 32);
                    uint32_t bA[2] = { b0, b1 };
                    uint32_t bB[2] = { b2, b3 };
                    mma_f16(ctx[2 * ntp],     a, bA);
                    mma_f16(ctx[2 * ntp + 1], a, bB);
                }
            }
        }
        __syncthreads();
    }

    // ---- write ctx ----
    {
        const int wm1 = warp * 16;
        float inv1 = 1.0f / lrow[wm1 + gid];
        float inv2 = 1.0f / lrow[wm1 + gid + 8];
        size_t row1 = qrow0 + wm1 + gid;
        size_t row2 = row1 + 8;
        #pragma unroll
        for (int nt = 0; nt < 8; nt++) {
            int col = nt * 8 + 2 * tig;
            *(__half2*)(CTH + row1 * H_ + hoff + col) =
                __floats2half2_rn(ctx[nt][0] * inv1, ctx[nt][1] * inv1);
            *(__half2*)(CTH + row2 * H_ + hoff + col) =
                __floats2half2_rn(ctx[nt][2] * inv2, ctx[nt][3] * inv2);
        }
    }
}

// ---------------- LayerNorm over H=768, one row per CTA ----------------------
__global__ void __launch_bounds__(256) ln_kernel(
    const float* __restrict__ X, const float* __restrict__ gam,
    const float* __restrict__ bet, float* __restrict__ out)
{
    const int row = blockIdx.x;
    const int t   = threadIdx.x;
    const float* x = X + (size_t)row * H_;
    float v0 = x[t], v1 = x[t + 256], v2 = x[t + 512];
    float s = v0 + v1 + v2;
    float q = v0 * v0 + v1 * v1 + v2 * v2;

    __shared__ float sh[64];
    #pragma unroll
    for (int o = 16; o > 0; o >>= 1) {
        s += __shfl_down_sync(0xffffffffu, s, o);
        q += __shfl_down_sync(0xffffffffu, q, o);
    }
    int w = t >> 5, lane = t & 31;
    if (lane == 0) { sh[w] = s; sh[32 + w] = q; }
    __syncthreads();
    if (t == 0) {
        float ts = 0.f, tq = 0.f;
        #pragma unroll
        for (int i = 0; i < 8; i++) { ts += sh[i]; tq += sh[32 + i]; }
        sh[0] = ts;
        sh[32] = tq;
    }
    __syncthreads();
    float mu  = sh[0] * (1.0f / 768.0f);
    float var = sh[32] * (1.0f / 768.0f) - mu * mu;
    float r   = rsqrtf(var + 1e-7f);

    float* o = out + (size_t)row * H_;
    o[t]       = (v0 - mu) * r * gam[t]       + bet[t];
    o[t + 256] = (v1 - mu) * r * gam[t + 256] + bet[t + 256];
    o[t + 512] = (v2 - mu) * r * gam[t + 512] + bet[t + 512];
}

// ---------------- launch ------------------------------------------------------
extern "C" void kernel_launch(void* const* d_in, const int* in_sizes, int n_in,
                              void* d_out, int out_size)
{
    const float* hidden = (const float*)d_in[0];
    const float* rel    = (const float*)d_in[1];
    const float* Wq = (const float*)d_in[2];  const float* bq = (const float*)d_in[3];
    const float* Wk = (const float*)d_in[4];  const float* bk = (const float*)d_in[5];
    const float* Wv = (const float*)d_in[6];  const float* bv = (const float*)d_in[7];
    const float* Wo = (const float*)d_in[8];  const float* bo = (const float*)d_in[9];
    const float* lns = (const float*)d_in[10];
    const float* lnb = (const float*)d_in[11];
    float* out = (float*)d_out;

    __half *HH, *RELH, *WTh, *Qh, *Kh, *Vh, *CTH, *PKH, *PQH;
    float *PK, *PQ, *XR;
    cudaGetSymbolAddress((void**)&HH,   g_HH);
    cudaGetSymbolAddress((void**)&RELH, g_RELH);
    cudaGetSymbolAddress((void**)&WTh,  g_WTh);
    cudaGetSymbolAddress((void**)&Qh,   g_Qh);
    cudaGetSymbolAddress((void**)&Kh,   g_Kh);
    cudaGetSymbolAddress((void**)&Vh,   g_Vh);
    cudaGetSymbolAddress((void**)&CTH,  g_CTH);
    cudaGetSymbolAddress((void**)&PK,   g_PK);
    cudaGetSymbolAddress((void**)&PQ,   g_PQ);
    cudaGetSymbolAddress((void**)&PKH,  g_PKH);
    cudaGetSymbolAddress((void**)&PQH,  g_PQH);
    cudaGetSymbolAddress((void**)&XR,   g_XR);

    const int M = B_ * S_;                       // 32768

    // conversions (one transpose launch for all 4 weights)
    f2h_kernel<<<TOT_ / 1024, 256>>>(hidden, HH);
    f2h_kernel<<<(512 * H_) / 1024, 256>>>(rel, RELH);
    transpose768h4<<<dim3(24, 24, 4), dim3(32, 8)>>>(Wq, Wk, Wv, Wo, WTh);

    cudaFuncSetAttribute(qkv_gemm,
                         cudaFuncAttributeMaxDynamicSharedMemorySize, GSMEM);
    cudaFuncSetAttribute(pos_gemm,
                         cudaFuncAttributeMaxDynamicSharedMemorySize, GSMEM);
    cudaFuncSetAttribute(out_gemm,
                         cudaFuncAttributeMaxDynamicSharedMemorySize, GSMEM);

    // QKV in one launch; pos projections in one launch (128-thread CTAs)
    qkv_gemm<<<dim3(18, M / 128), 128, GSMEM>>>(HH, WTh, bq, bk, bv, Qh, Kh, Vh);
    pos_gemm<<<dim3(12, 512 / 128), 128, GSMEM>>>(RELH, WTh, bq, bk, PK, PQ);
    build_pos_h<<<511, 768>>>(PK, PQ, PKH, PQH);

    // attention
    const int smem_attn =
        (128 * QSTU * 3 + 128 * PSTU) * 4 + (128 * SST + 3 * 128) * 4;
    cudaFuncSetAttribute(attn_mma,
                         cudaFuncAttributeMaxDynamicSharedMemorySize, smem_attn);
    attn_mma<<<dim3(NH_, NB_, B_), 256, smem_attn>>>(Qh, Kh, Vh, PKH, PQH, CTH);

    // output projection + residual, then layernorm
    out_gemm<<<dim3(6, M / 128), 128, GSMEM>>>(CTH, WTh + (size_t)3 * H_ * H_,
                                               bo, hidden, XR);
    ln_kernel<<<M, 256>>>(XR, lns, lnb, out);
}

// round 15
// speedup vs baseline: 1.1493x; 1.1493x over previous
#include <cuda_runtime.h>
#include <cuda_fp16.h>
#include <math.h>
#include <stdint.h>

#define B_   4
#define S_   8192
#define H_   768
#define NH_  12
#define HD_  64
#define NB_  64
#define TOT_ (B_*S_*H_)

// attention smem strides
#define QSTU 36    // u32 stride for fp16 Q/K/V rows
#define PSTU 68    // u32 stride for fp16 P rows
#define SST  132   // fp32 score stride (even)
#define KVSZ (128 * QSTU)

// fp16 gemm config: BK=32 halves
#define GST   20
#define GSTG  (128 * GST)
#define GNSTG 3
#define GKT   24
#define GSMEM (2 * GNSTG * GSTG * 4)   // 61440 B

// ---------------- scratch (device globals; no allocs allowed) ----------------
__device__ __half g_HH[TOT_];
__device__ __half g_RELH[512 * H_];
__device__ __half g_WTh[4 * H_ * H_];
__device__ __half g_Qh[TOT_];
__device__ __half g_Kh[TOT_];
__device__ __half g_Vh[TOT_];
__device__ __half g_CTH[TOT_];
__device__ float  g_XR[TOT_];
__device__ float  g_PK[512 * H_];
__device__ float  g_PQ[512 * H_];
__device__ __half g_PKH[NH_ * 512 * HD_];
__device__ __half g_PQH[NH_ * 512 * HD_];

// ---------------- helpers -----------------------------------------------------
__device__ __forceinline__ void mma_f16(float* c, const uint32_t* a, const uint32_t* b) {
    asm volatile(
        "mma.sync.aligned.m16n8k16.row.col.f32.f16.f16.f32 "
        "{%0,%1,%2,%3},{%4,%5,%6,%7},{%8,%9},{%0,%1,%2,%3};\n"
        : "+f"(c[0]), "+f"(c[1]), "+f"(c[2]), "+f"(c[3])
        : "r"(a[0]), "r"(a[1]), "r"(a[2]), "r"(a[3]), "r"(b[0]), "r"(b[1]));
}

__device__ __forceinline__ void ldsm_x4(
    uint32_t& r0, uint32_t& r1, uint32_t& r2, uint32_t& r3, uint32_t addr)
{
    asm volatile(
        "ldmatrix.sync.aligned.m8n8.x4.shared.b16 {%0,%1,%2,%3}, [%4];"
        : "=r"(r0), "=r"(r1), "=r"(r2), "=r"(r3) : "r"(addr));
}

__device__ __forceinline__ void ldsm_x4_t(
    uint32_t& r0, uint32_t& r1, uint32_t& r2, uint32_t& r3, uint32_t addr)
{
    asm volatile(
        "ldmatrix.sync.aligned.m8n8.x4.trans.shared.b16 {%0,%1,%2,%3}, [%4];"
        : "=r"(r0), "=r"(r1), "=r"(r2), "=r"(r3) : "r"(addr));
}

__device__ __forceinline__ void cp16u(uint32_t* dst_smem, const void* src) {
    uint32_t d = (uint32_t)__cvta_generic_to_shared(dst_smem);
    asm volatile("cp.async.cg.shared.global [%0], [%1], 16;\n" :: "r"(d), "l"(src));
}
__device__ __forceinline__ void cp_commit() {
    asm volatile("cp.async.commit_group;\n");
}

__device__ __forceinline__ uint32_t ex2_f16x2(uint32_t x) {
    uint32_t r;
    asm volatile("ex2.approx.f16x2 %0, %1;" : "=r"(r) : "r"(x));
    return r;
}

// ---------------- conversion kernels -----------------------------------------
__global__ void __launch_bounds__(256) f2h_kernel(
    const float* __restrict__ x, __half* __restrict__ y)
{
    size_t i = ((size_t)blockIdx.x * 256 + threadIdx.x) * 4;
    float4 v = *(const float4*)(x + i);
    *(__half2*)(y + i)     = __floats2half2_rn(v.x, v.y);
    *(__half2*)(y + i + 2) = __floats2half2_rn(v.z, v.w);
}

// 4 weights transposed in one launch: WT[z][n][k] = fp16(W[z][k][n])
__global__ void __launch_bounds__(256) transpose768h4(
    const float* __restrict__ W0, const float* __restrict__ W1,
    const float* __restrict__ W2, const float* __restrict__ W3,
    __half* __restrict__ WT)
{
    __shared__ float t[32][33];
    const float* W = (blockIdx.z == 0) ? W0 : (blockIdx.z == 1) ? W1
                   : (blockIdx.z == 2) ? W2 : W3;
    __half* WTz = WT + (size_t)blockIdx.z * H_ * H_;
    int x = blockIdx.x * 32 + threadIdx.x;
    int y = blockIdx.y * 32 + threadIdx.y;
    #pragma unroll
    for (int i = 0; i < 32; i += 8)
        t[threadIdx.y + i][threadIdx.x] = W[(size_t)(y + i) * H_ + x];
    __syncthreads();
    x = blockIdx.y * 32 + threadIdx.x;
    y = blockIdx.x * 32 + threadIdx.y;
    #pragma unroll
    for (int i = 0; i < 32; i += 8)
        WTz[(size_t)(y + i) * H_ + x] = __float2half_rn(t[threadIdx.x][threadIdx.y + i]);
}

// ---------------- shared GEMM body (round-13 shape): 8 warps of 32x64 --------
__device__ __forceinline__ void gemm_body(
    const __half* __restrict__ A, const __half* __restrict__ Bw,
    const float* __restrict__ bias, const float* __restrict__ Rres,
    float* __restrict__ Cf, __half* __restrict__ Ch,
    int bm, int bn, uint32_t* gsm)
{
    uint32_t* As = gsm;
    uint32_t* Bs = gsm + GNSTG * GSTG;

    const int tid  = threadIdx.x;
    const int lane = tid & 31;
    const int warp = tid >> 5;
    const int wm   = (warp & 3) * 32;
    const int wn   = (warp >> 2) * 64;
    const int gid  = lane >> 2;
    const int tig  = lane & 3;
    const int lr16 = lane & 15;
    const int lc4  = (lane >> 4) << 2;

    const int fr = tid >> 1;
    const int fc = (tid & 1) << 1;

    const uint32_t as0 = (uint32_t)__cvta_generic_to_shared(As);
    const uint32_t bs0 = (uint32_t)__cvta_generic_to_shared(Bs);

    float acc[2][8][4];
    #pragma unroll
    for (int mt = 0; mt < 2; mt++)
        #pragma unroll
        for (int nt = 0; nt < 8; nt++)
            #pragma unroll
            for (int i = 0; i < 4; i++) acc[mt][nt][i] = 0.f;

    auto fill = [&](int s, int kt) {
        const int kb = kt * 32;
        const __half* Ab = A  + (size_t)(bm + fr) * H_ + kb;
        const __half* Bb = Bw + (size_t)(bn + fr) * H_ + kb;
        uint32_t* as = As + s * GSTG + fr * GST;
        uint32_t* bs = Bs + s * GSTG + fr * GST;
        cp16u(&as[fc * 4],       Ab + fc * 8);
        cp16u(&as[(fc + 1) * 4], Ab + (fc + 1) * 8);
        cp16u(&bs[fc * 4],       Bb + fc * 8);
        cp16u(&bs[(fc + 1) * 4], Bb + (fc + 1) * 8);
        cp_commit();
    };

    fill(0, 0);
    fill(1, 1);

    for (int kt = 0; kt < GKT; kt++) {
        if (kt < GKT - 1) asm volatile("cp.async.wait_group 1;\n");
        else              asm volatile("cp.async.wait_group 0;\n");
        __syncthreads();

        const uint32_t asb = as0 + (uint32_t)((kt % GNSTG) * GSTG) * 4;
        const uint32_t bsb = bs0 + (uint32_t)((kt % GNSTG) * GSTG) * 4;

        #pragma unroll
        for (int ks = 0; ks < 2; ks++) {
            const int wb = ks * 8;
            uint32_t a[2][4], b[8][2];
            #pragma unroll
            for (int mt = 0; mt < 2; mt++)
                ldsm_x4(a[mt][0], a[mt][1], a[mt][2], a[mt][3],
                        asb + (uint32_t)(((wm + mt * 16 + lr16) * GST + wb + lc4) * 4));
            #pragma unroll
            for (int ntp = 0; ntp < 4; ntp++) {
                uint32_t r0, r1, r2, r3;
                ldsm_x4(r0, r1, r2, r3,
                        bsb + (uint32_t)(((wn + ntp * 16 + lr16) * GST + wb + lc4) * 4));
                b[2 * ntp][0]     = r0;
                b[2 * ntp + 1][0] = r1;
                b[2 * ntp][1]     = r2;
                b[2 * ntp + 1][1] = r3;
            }
            #pragma unroll
            for (int mt = 0; mt < 2; mt++)
                #pragma unroll
                for (int nt = 0; nt < 8; nt++)
                    mma_f16(acc[mt][nt], a[mt], b[nt]);
        }
        if (kt + 2 < GKT) fill((kt + 2) % GNSTG, kt + 2);
    }

    #pragma unroll
    for (int mt = 0; mt < 2; mt++) {
        #pragma unroll
        for (int hi = 0; hi < 2; hi++) {
            size_t row = (size_t)bm + wm + mt * 16 + gid + hi * 8;
            #pragma unroll
            for (int nt = 0; nt < 8; nt++) {
                int col = bn + wn + nt * 8 + tig * 2;
                float v0 = acc[mt][nt][hi * 2 + 0] + bias[col];
                float v1 = acc[mt][nt][hi * 2 + 1] + bias[col + 1];
                if (Rres != nullptr) {
                    float2 rr = *(const float2*)(Rres + row * (size_t)H_ + col);
                    v0 += rr.x; v1 += rr.y;
                }
                if (Cf != nullptr)
                    *(float2*)(Cf + row * (size_t)H_ + col) = make_float2(v0, v1);
                else
                    *(__half2*)(Ch + row * (size_t)H_ + col) = __floats2half2_rn(v0, v1);
            }
        }
    }
}

// QKV in one launch: blockIdx.x/6 selects {Q,K,V}
__global__ void __launch_bounds__(256, 2) qkv_gemm(
    const __half* __restrict__ A, const __half* __restrict__ WT,
    const float* __restrict__ bq, const float* __restrict__ bk,
    const float* __restrict__ bv,
    __half* __restrict__ Oq, __half* __restrict__ Ok, __half* __restrict__ Ov)
{
    extern __shared__ uint32_t gsm[];
    const int which = blockIdx.x / 6;
    const int bn = (blockIdx.x % 6) * 128;
    const int bm = blockIdx.y * 128;
    const __half* Bw = WT + (size_t)which * H_ * H_;
    const float* bias = (which == 0) ? bq : (which == 1) ? bk : bv;
    __half* Ch = (which == 0) ? Oq : (which == 1) ? Ok : Ov;
    gemm_body(A, Bw, bias, nullptr, nullptr, Ch, bm, bn, gsm);
}

__global__ void __launch_bounds__(256, 2) pos_gemm(
    const __half* __restrict__ A, const __half* __restrict__ WT,
    const float* __restrict__ bq, const float* __restrict__ bk,
    float* __restrict__ Opk, float* __restrict__ Opq)
{
    extern __shared__ uint32_t gsm[];
    const int which = blockIdx.x / 6;
    const int bn = (blockIdx.x % 6) * 128;
    const int bm = blockIdx.y * 128;
    const __half* Bw = WT + (size_t)(which == 0 ? 1 : 0) * H_ * H_;
    const float* bias = (which == 0) ? bk : bq;
    float* Cf = (which == 0) ? Opk : Opq;
    gemm_body(A, Bw, bias, nullptr, Cf, nullptr, bm, bn, gsm);
}

__global__ void __launch_bounds__(256, 2) out_gemm(
    const __half* __restrict__ A, const __half* __restrict__ WT,
    const float* __restrict__ bias, const float* __restrict__ Rres,
    float* __restrict__ Cf)
{
    extern __shared__ uint32_t gsm[];
    const int bn = blockIdx.x * 128;
    const int bm = blockIdx.y * 128;
    gemm_body(A, WT, bias, Rres, Cf, nullptr, bm, bn, gsm);
}

// ---------------- bucketization + fp16 pos tables ----------------------------
__device__ __forceinline__ int bucket_idx_dev(int d)
{
    int ad = d < 0 ? -d : d;
    int v;
    if (ad <= 128) {
        v = d;
    } else {
        float t = logf((float)ad / 128.0f);
        t = t / 0.6892332713f;                   // fp32(ln(255/128))
        t = t * 127.0f;
        float lp = ceilf(t) + 128.0f;
        v = (int)(d < 0 ? -lp : lp);
    }
    v += 256;
    return v < 0 ? 0 : (v > 511 ? 511 : v);
}

__global__ void build_pos_h(const float* __restrict__ PK, const float* __restrict__ PQ,
                            __half* __restrict__ PKH, __half* __restrict__ PQH)
{
    int dd = blockIdx.x;
    int t  = threadIdx.x;
    int p  = bucket_idx_dev(dd - 383);
    int h  = t >> 6;
    int d  = t & 63;
    size_t dst = ((size_t)h * 512 + dd + 1) * HD_ + d;
    PKH[dst] = __float2half_rn(PK[(size_t)p * H_ + t]);
    PQH[dst] = __float2half_rn(PQ[(size_t)p * H_ + t]);
    if (dd == 0) {
        PKH[((size_t)h * 512) * HD_ + d] = __float2half_rn(0.f);
        PQH[((size_t)h * 512) * HD_ + d] = __float2half_rn(0.f);
    }
}

// ---------------- attention: exact-window C2P/P2C + K/V cp.async prefetch ----
__global__ void __launch_bounds__(256, 1) attn_mma(
    const __half* __restrict__ Qh, const __half* __restrict__ Kh,
    const __half* __restrict__ Vh,
    const __half* __restrict__ PKH, const __half* __restrict__ PQH,
    __half* __restrict__ CTH)
{
    extern __shared__ char smc[];
    uint32_t* Qsu  = (uint32_t*)smc;                      // 128*QSTU
    uint32_t* Ksu0 = Qsu + 128 * QSTU;                    // 2 buffers
    uint32_t* Vsu0 = Ksu0 + 2 * KVSZ;                     // 2 buffers
    uint32_t* Phu  = Vsu0 + 2 * KVSZ;                     // 128*PSTU
    float* Ss   = (float*)(Phu + 128 * PSTU);             // 128*SST
    float* mrow = Ss + 128 * SST;
    float* lrow = mrow + 128;
    float* crow = lrow + 128;

    const int h = blockIdx.x, n = blockIdx.y, b = blockIdx.z;
    const int tid  = threadIdx.x;
    const int lane = tid & 31;
    const int warp = tid >> 5;
    const int gid  = lane >> 2;
    const int tig  = lane & 3;
    const int lr16 = lane & 15;
    const int lc4  = (lane >> 4) << 2;
    const size_t qrow0 = (size_t)b * S_ + (size_t)n * 128;
    const size_t hoff  = (size_t)h * HD_;

    const uint32_t qbase  = (uint32_t)__cvta_generic_to_shared(Qsu);
    const uint32_t kbase0 = (uint32_t)__cvta_generic_to_shared(Ksu0);
    const uint32_t vbase0 = (uint32_t)__cvta_generic_to_shared(Vsu0);
    const uint32_t pbase  = (uint32_t)__cvta_generic_to_shared(Phu);

    // K/V prefetch into buffer s for chunk cc (cp.async; zero-fill OOB rows)
    auto stagekv = [&](int s, int cc) {
        const long sk0 = (long)n * 128 - 128 + cc * 128;
        const int r  = tid >> 1;
        const int qd = tid & 1;
        long srow = sk0 + r;
        uint32_t* kb = Ksu0 + s * KVSZ + r * QSTU + qd * 16;
        uint32_t* vb = Vsu0 + s * KVSZ + r * QSTU + qd * 16;
        if (srow >= 0 && srow < S_) {
            const __half* gk = Kh + ((size_t)b * S_ + srow) * H_ + hoff + qd * 32;
            const __half* gv = Vh + ((size_t)b * S_ + srow) * H_ + hoff + qd * 32;
            #pragma unroll
            for (int u = 0; u < 4; u++) {
                cp16u(kb + u * 4, gk + u * 8);
                cp16u(vb + u * 4, gv + u * 8);
            }
        } else {
            #pragma unroll
            for (int u = 0; u < 4; u++) {
                *(uint4*)(kb + u * 4) = make_uint4(0u, 0u, 0u, 0u);
                *(uint4*)(vb + u * 4) = make_uint4(0u, 0u, 0u, 0u);
            }
        }
        cp_commit();
    };

    stagekv(0, 0);                        // prefetch chunk 0

    for (int i = tid; i < 128 * 8; i += 256) {
        int r = i >> 3, c = i & 7;
        uint4 v = *(const uint4*)(Qh + (qrow0 + r) * H_ + hoff + c * 8);
        uint32_t* d = &Qsu[r * QSTU + c * 4];
        d[0] = v.x; d[1] = v.y; d[2] = v.z; d[3] = v.w;
    }
    if (tid < 128) { mrow[tid] = -1e30f; lrow[tid] = 0.f; }

    float ctx[8][4];
    #pragma unroll
    for (int nt = 0; nt < 8; nt++)
        #pragma unroll
        for (int i = 0; i < 4; i++) ctx[nt][i] = 0.f;

    const uint32_t* pk32 = (const uint32_t*)PKH + (size_t)h * 512 * 32;
    const uint32_t* pq32 = (const uint32_t*)PQH + (size_t)h * 512 * 32;
    const float scale = 0.07216878364870323f;    // 1/sqrt(192)
    const float L2E   = 1.4426950408889634f;

    const int lg  = lane >> 3;
    const int lr  = lane & 7;
    const int vkb = (lg & 1) * 8 + lr;
    const int vnb = (lg >> 1) * 8;

    for (int c = 0; c < 3; c++) {
        asm volatile("cp.async.wait_group 0;\n");
        __syncthreads();
        if (c < 2) stagekv((c + 1) & 1, c + 1);   // overlap with compute

        const uint32_t kbase = kbase0 + (uint32_t)((c & 1) * KVSZ) * 4;
        const uint32_t vbase = vbase0 + (uint32_t)((c & 1) * KVSZ) * 4;
        const int c0 = c * 128;

        // ---- c2c ----
        {
            const int wm = (warp & 3) * 32, wn = (warp >> 2) * 64;
            float acc[2][8][4];
            #pragma unroll
            for (int mt = 0; mt < 2; mt++)
                #pragma unroll
                for (int nt = 0; nt < 8; nt++)
                    #pragma unroll
                    for (int i = 0; i < 4; i++) acc[mt][nt][i] = 0.f;

            #pragma unroll
            for (int ks = 0; ks < 4; ks++) {
                const int wb = ks * 8;
                uint32_t a[2][4], bf[8][2];
                #pragma unroll
                for (int mt = 0; mt < 2; mt++)
                    ldsm_x4(a[mt][0], a[mt][1], a[mt][2], a[mt][3],
                            qbase + (uint32_t)(((wm + mt * 16 + lr16) * QSTU + wb + lc4) * 4));
                #pragma unroll
                for (int ntp = 0; ntp < 4; ntp++) {
                    uint32_t r0, r1, r2, r3;
                    ldsm_x4(r0, r1, r2, r3,
                            kbase + (uint32_t)(((wn + ntp * 16 + lr16) * QSTU + wb + lc4) * 4));
                    bf[2 * ntp][0]     = r0;
                    bf[2 * ntp + 1][0] = r1;
                    bf[2 * ntp][1]     = r2;
                    bf[2 * ntp + 1][1] = r3;
                }
                #pragma unroll
                for (int mt = 0; mt < 2; mt++)
                    #pragma unroll
                    for (int nt = 0; nt < 8; nt++)
                        mma_f16(acc[mt][nt], a[mt], bf[nt]);
            }
            #pragma unroll
            for (int mt = 0; mt < 2; mt++) {
                int r1 = wm + mt * 16 + gid;
                #pragma unroll
                for (int nt = 0; nt < 8; nt++) {
                    int cc = wn + nt * 8 + 2 * tig;
                    *(float2*)&Ss[r1 * SST + cc] =
                        make_float2(acc[mt][nt][0], acc[mt][nt][1]);
                    *(float2*)&Ss[(r1 + 8) * SST + cc] =
                        make_float2(acc[mt][nt][2], acc[mt][nt][3]);
                }
            }
        }
        __syncthreads();

        // ---- C2P: exact window [wm, wm+160), warp pair splits 80+80 ---------
        {
            const int wm = (warp & 3) * 32;
            const int wg = warp >> 2;
            const int colbase = 256 - c0;
            const int ws = wm + wg * 80;
            float acc[2][10][4];
            #pragma unroll
            for (int mt = 0; mt < 2; mt++)
                #pragma unroll
                for (int nt = 0; nt < 10; nt++)
                    #pragma unroll
                    for (int i = 0; i < 4; i++) acc[mt][nt][i] = 0.f;

            #pragma unroll
            for (int ks = 0; ks < 4; ks++) {
                const int wb = ks * 8;
                uint32_t a[2][4];
                #pragma unroll
                for (int mt = 0; mt < 2; mt++)
                    ldsm_x4(a[mt][0], a[mt][1], a[mt][2], a[mt][3],
                            qbase + (uint32_t)(((wm + mt * 16 + lr16) * QSTU + wb + lc4) * 4));
                #pragma unroll
                for (int nt = 0; nt < 10; nt++) {
                    int cc = colbase + ws + nt * 8 + gid;
                    uint32_t bf[2];
                    bf[0] = __ldg(&pk32[(size_t)cc * 32 + wb + tig]);
                    bf[1] = __ldg(&pk32[(size_t)cc * 32 + wb + 4 + tig]);
                    mma_f16(acc[0][nt], a[0], bf);
                    mma_f16(acc[1][nt], a[1], bf);
                }
            }
            #pragma unroll
            for (int mt = 0; mt < 2; mt++) {
                int r1 = wm + mt * 16 + gid;
                #pragma unroll
                for (int nt = 0; nt < 10; nt++) {
                    int ci = ws + nt * 8 + 2 * tig;
                    int jj;
                    jj = r1 - ci + 128;
                    if (jj >= 0 && jj < 128) Ss[r1 * SST + jj] += acc[mt][nt][0];
                    jj = r1 - ci + 127;
                    if (jj >= 0 && jj < 128) Ss[r1 * SST + jj] += acc[mt][nt][1];
                    int r2 = r1 + 8;
                    jj = r2 - ci + 128;
                    if (jj >= 0 && jj < 128) Ss[r2 * SST + jj] += acc[mt][nt][2];
                    jj = r2 - ci + 127;
                    if (jj >= 0 && jj < 128) Ss[r2 * SST + jj] += acc[mt][nt][3];
                }
            }
        }
        __syncthreads();

        // ---- P2C: exact window [96-wm, 256-wm), warp pair splits 80+80 ------
        {
            const int wm = (warp & 3) * 32;
            const int wg = warp >> 2;
            const int colbase = 256 - c0;
            const int ws = (96 - wm) + wg * 80;
            float acc[2][10][4];
            #pragma unroll
            for (int mt = 0; mt < 2; mt++)
                #pragma unroll
                for (int nt = 0; nt < 10; nt++)
                    #pragma unroll
                    for (int i = 0; i < 4; i++) acc[mt][nt][i] = 0.f;

            #pragma unroll
            for (int ks = 0; ks < 4; ks++) {
                const int wb = ks * 8;
                uint32_t a[2][4];
                #pragma unroll
                for (int mt = 0; mt < 2; mt++)
                    ldsm_x4(a[mt][0], a[mt][1], a[mt][2], a[mt][3],
                            kbase + (uint32_t)(((wm + mt * 16 + lr16) * QSTU + wb + lc4) * 4));
                #pragma unroll
                for (int nt = 0; nt < 10; nt++) {
                    int cc = colbase + ws + nt * 8 + gid;
                    uint32_t bf[2];
                    bf[0] = __ldg(&pq32[(size_t)cc * 32 + wb + tig]);
                    bf[1] = __ldg(&pq32[(size_t)cc * 32 + wb + 4 + tig]);
                    mma_f16(acc[0][nt], a[0], bf);
                    mma_f16(acc[1][nt], a[1], bf);
                }
            }
            #pragma unroll
            for (int mt = 0; mt < 2; mt++) {
                int r1 = wm + mt * 16 + gid;
                #pragma unroll
                for (int nt = 0; nt < 10; nt++) {
                    int ci = ws + nt * 8 + 2 * tig;
                    int q;
                    q = r1 + ci - 128;
                    if (q >= 0 && q < 128) Ss[q * SST + r1] += acc[mt][nt][0];
                    q = r1 + ci - 127;
                    if (q >= 0 && q < 128) Ss[q * SST + r1] += acc[mt][nt][1];
                    int r2 = r1 + 8;
                    q = r2 + ci - 128;
                    if (q >= 0 && q < 128) Ss[q * SST + r2] += acc[mt][nt][2];
                    q = r2 + ci - 127;
                    if (q >= 0 && q < 128) Ss[q * SST + r2] += acc[mt][nt][3];
                }
            }
        }
        __syncthreads();

        // ---- online softmax: lane-pair per row, shuffle reductions, ex2 -----
        {
            const int r  = tid >> 1;
            const int hh = tid & 1;
            float* srow = Ss + r * SST + hh * 64;
            float mx = -1e30f;
            #pragma unroll 8
            for (int j = 0; j < 64; j++) mx = fmaxf(mx, srow[j]);
            mx = fmaxf(mx, __shfl_xor_sync(0xffffffffu, mx, 1));

            float mold = mrow[r];
            float mnew = fmaxf(mold, mx * scale);
            float corr = exp2f((mold - mnew) * L2E);

            const float sl = scale * L2E;
            const float ml = mnew * L2E;
            float ssum = 0.f;
            uint32_t* prow = Phu + r * PSTU + hh * 32;
            #pragma unroll 8
            for (int j = 0; j < 64; j += 2) {
                float t0 = fmaf(srow[j],     sl, -ml);
                float t1 = fmaf(srow[j + 1], sl, -ml);
                __half2 th = __floats2half2_rn(t0, t1);
                uint32_t ph = ex2_f16x2(*(uint32_t*)&th);
                prow[j >> 1] = ph;
                float2 pf = __half22float2(*(__half2*)&ph);
                ssum += pf.x + pf.y;
            }
            ssum += __shfl_xor_sync(0xffffffffu, ssum, 1);
            if (hh == 0) {
                crow[r] = corr;
                mrow[r] = mnew;
                lrow[r] = lrow[r] * corr + ssum;
            }
        }
        __syncthreads();

        // ---- PV ----
        {
            const int wm1 = warp * 16;
            float c1 = crow[wm1 + gid], c2 = crow[wm1 + gid + 8];
            #pragma unroll
            for (int nt = 0; nt < 8; nt++) {
                ctx[nt][0] *= c1; ctx[nt][1] *= c1;
                ctx[nt][2] *= c2; ctx[nt][3] *= c2;
            }
            #pragma unroll
            for (int ks = 0; ks < 8; ks++) {
                uint32_t a[4];
                ldsm_x4(a[0], a[1], a[2], a[3],
                        pbase + (uint32_t)(((wm1 + lr16) * PSTU + ks * 8 + lc4) * 4));
                uint32_t vaddr = vbase +
                    (uint32_t)((16 * ks + vkb) * (QSTU * 4)) + (uint32_t)(vnb * 2);
                #pragma unroll
                for (int ntp = 0; ntp < 4; ntp++) {
                    uint32_t b0, b1, b2, b3;
                    ldsm_x4_t(b0, b1, b2, b3, vaddr + ntp * 32);
                    uint32_t bA[2] = { b0, b1 };
                    uint32_t bB[2] = { b2, b3 };
                    mma_f16(ctx[2 * ntp],     a, bA);
                    mma_f16(ctx[2 * ntp + 1], a, bB);
                }
            }
        }
        __syncthreads();
    }

    // ---- write ctx ----
    {
        const int wm1 = warp * 16;
        float inv1 = 1.0f / lrow[wm1 + gid];
        float inv2 = 1.0f / lrow[wm1 + gid + 8];
        size_t row1 = qrow0 + wm1 + gid;
        size_t row2 = row1 + 8;
        #pragma unroll
        for (int nt = 0; nt < 8; nt++) {
            int col = nt * 8 + 2 * tig;
            *(__half2*)(CTH + row1 * H_ + hoff + col) =
                __floats2half2_rn(ctx[nt][0] * inv1, ctx[nt][1] * inv1);
            *(__half2*)(CTH + row2 * H_ + hoff + col) =
                __floats2half2_rn(ctx[nt][2] * inv2, ctx[nt][3] * inv2);
        }
    }
}

// ---------------- LayerNorm over H=768, one row per CTA ----------------------
__global__ void __launch_bounds__(256) ln_kernel(
    const float* __restrict__ X, const float* __restrict__ gam,
    const float* __restrict__ bet, float* __restrict__ out)
{
    const int row = blockIdx.x;
    const int t   = threadIdx.x;
    const float* x = X + (size_t)row * H_;
    float v0 = x[t], v1 = x[t + 256], v2 = x[t + 512];
    float s = v0 + v1 + v2;
    float q = v0 * v0 + v1 * v1 + v2 * v2;

    __shared__ float sh[64];
    #pragma unroll
    for (int o = 16; o > 0; o >>= 1) {
        s += __shfl_down_sync(0xffffffffu, s, o);
        q += __shfl_down_sync(0xffffffffu, q, o);
    }
    int w = t >> 5, lane = t & 31;
    if (lane == 0) { sh[w] = s; sh[32 + w] = q; }
    __syncthreads();
    if (t == 0) {
        float ts = 0.f, tq = 0.f;
        #pragma unroll
        for (int i = 0; i < 8; i++) { ts += sh[i]; tq += sh[32 + i]; }
        sh[0] = ts;
        sh[32] = tq;
    }
    __syncthreads();
    float mu  = sh[0] * (1.0f / 768.0f);
    float var = sh[32] * (1.0f / 768.0f) - mu * mu;
    float r   = rsqrtf(var + 1e-7f);

    float* o = out + (size_t)row * H_;
    o[t]       = (v0 - mu) * r * gam[t]       + bet[t];
    o[t + 256] = (v1 - mu) * r * gam[t + 256] + bet[t + 256];
    o[t + 512] = (v2 - mu) * r * gam[t + 512] + bet[t + 512];
}

// ---------------- launch ------------------------------------------------------
extern "C" void kernel_launch(void* const* d_in, const int* in_sizes, int n_in,
                              void* d_out, int out_size)
{
    const float* hidden = (const float*)d_in[0];
    const float* rel    = (const float*)d_in[1];
    const float* Wq = (const float*)d_in[2];  const float* bq = (const float*)d_in[3];
    const float* Wk = (const float*)d_in[4];  const float* bk = (const float*)d_in[5];
    const float* Wv = (const float*)d_in[6];  const float* bv = (const float*)d_in[7];
    const float* Wo = (const float*)d_in[8];  const float* bo = (const float*)d_in[9];
    const float* lns = (const float*)d_in[10];
    const float* lnb = (const float*)d_in[11];
    float* out = (float*)d_out;

    __half *HH, *RELH, *WTh, *Qh, *Kh, *Vh, *CTH, *PKH, *PQH;
    float *PK, *PQ, *XR;
    cudaGetSymbolAddress((void**)&HH,   g_HH);
    cudaGetSymbolAddress((void**)&RELH, g_RELH);
    cudaGetSymbolAddress((void**)&WTh,  g_WTh);
    cudaGetSymbolAddress((void**)&Qh,   g_Qh);
    cudaGetSymbolAddress((void**)&Kh,   g_Kh);
    cudaGetSymbolAddress((void**)&Vh,   g_Vh);
    cudaGetSymbolAddress((void**)&CTH,  g_CTH);
    cudaGetSymbolAddress((void**)&PK,   g_PK);
    cudaGetSymbolAddress((void**)&PQ,   g_PQ);
    cudaGetSymbolAddress((void**)&PKH,  g_PKH);
    cudaGetSymbolAddress((void**)&PQH,  g_PQH);
    cudaGetSymbolAddress((void**)&XR,   g_XR);

    const int M = B_ * S_;                       // 32768

    f2h_kernel<<<TOT_ / 1024, 256>>>(hidden, HH);
    f2h_kernel<<<(512 * H_) / 1024, 256>>>(rel, RELH);
    transpose768h4<<<dim3(24, 24, 4), dim3(32, 8)>>>(Wq, Wk, Wv, Wo, WTh);

    cudaFuncSetAttribute(qkv_gemm,
                         cudaFuncAttributeMaxDynamicSharedMemorySize, GSMEM);
    cudaFuncSetAttribute(pos_gemm,
                         cudaFuncAttributeMaxDynamicSharedMemorySize, GSMEM);
    cudaFuncSetAttribute(out_gemm,
                         cudaFuncAttributeMaxDynamicSharedMemorySize, GSMEM);

    qkv_gemm<<<dim3(18, M / 128), 256, GSMEM>>>(HH, WTh, bq, bk, bv, Qh, Kh, Vh);
    pos_gemm<<<dim3(12, 512 / 128), 256, GSMEM>>>(RELH, WTh, bq, bk, PK, PQ);
    build_pos_h<<<511, 768>>>(PK, PQ, PKH, PQH);

    // attention (Q + 2xK + 2xV + P + S + stats)
    const int smem_attn =
        (128 * QSTU * 5 + 128 * PSTU) * 4 + (128 * SST + 3 * 128) * 4;
    cudaFuncSetAttribute(attn_mma,
                         cudaFuncAttributeMaxDynamicSharedMemorySize, smem_attn);
    attn_mma<<<dim3(NH_, NB_, B_), 256, smem_attn>>>(Qh, Kh, Vh, PKH, PQH, CTH);

    out_gemm<<<dim3(6, M / 128), 256, GSMEM>>>(CTH, WTh + (size_t)3 * H_ * H_,
                                               bo, hidden, XR);
    ln_kernel<<<M, 256>>>(XR, lns, lnb, out);
}